// round 2
// baseline (speedup 1.0000x reference)
#include <cuda_runtime.h>
#include <cuda_bf16.h>

#define NHEADS 512
#define NK     64
#define SEQ    2048
#define NFFT   4096
#define NB     16

// Scratch (static __device__ — no allocation)
__device__ float  d_f[NHEADS * SEQ];
__device__ float2 d_Fhat[NHEADS * NFFT];
__device__ float2 d_tw[NFFT / 2];

__device__ __forceinline__ float2 cmul(float2 a, float2 b) {
    return make_float2(a.x * b.x - a.y * b.y, a.x * b.y + a.y * b.x);
}

// ---------------------------------------------------------------------------
// Twiddle table: d_tw[k] = exp(-2*pi*i*k/4096), k < 2048
// ---------------------------------------------------------------------------
__global__ void twiddle_kernel() {
    int k = blockIdx.x * blockDim.x + threadIdx.x;
    if (k < NFFT / 2) {
        float a = (float)k / (float)(NFFT / 2);  // k/2048 -> angle pi*a
        d_tw[k] = make_float2(cospif(a), -sinpif(a));
    }
}

// ---------------------------------------------------------------------------
// Filter construction.  Per head:
//   k_norm = L1norm(clip(k,1/16,1)); s[j]=1/(1+kn[j]); P[i]=prod_{j<i}s[j]
//   a_{t+1} = sum_j w[j] a_{t-j},  w[j]=m0[j]*P[j],  a_0=1
//   f_t     = sum_i g[i] a_{t-i},  g[i]=k[i]*P[i]
// Parallelized via T = C^64 (64 columns computed by 64 threads), then 32
// chunk matvecs produce a[0..2047], then the short g*a convolution gives f.
// ---------------------------------------------------------------------------
__global__ __launch_bounds__(64) void filter_kernel(const float* __restrict__ kin) {
    __shared__ float sh_kn[64], sh_P[64], sh_w[64], sh_g[64];
    __shared__ float sh_T[64 * 65];
    __shared__ float sh_V[64];
    __shared__ float sh_a[2048];
    __shared__ float part[2];

    const int tid = threadIdx.x;
    const int h   = blockIdx.x;

    float kv = kin[h * NK + tid];
    float kc = fminf(fmaxf(kv, 0.0625f), 1.0f);

    // block-sum of kc over 64 threads
    float v = kc;
    #pragma unroll
    for (int o = 16; o; o >>= 1) v += __shfl_xor_sync(0xffffffffu, v, o);
    if ((tid & 31) == 0) part[tid >> 5] = v;
    __syncthreads();
    float kn = kc / (part[0] + part[1]);
    sh_kn[tid] = kn;
    __syncthreads();

    if (tid == 0) {
        float p = 1.0f;
        for (int j = 0; j < 64; j++) {
            sh_P[j] = p;
            if (j < 63) p *= 1.0f / (1.0f + sh_kn[j]);
        }
    }
    __syncthreads();

    float m0 = (tid < 63) ? kn / (1.0f + kn) : 1.0f;
    sh_w[tid] = m0 * sh_P[tid];
    sh_g[tid] = kv * sh_P[tid];
    __syncthreads();

    // ---- Phase A: columns of T = C^64. Thread `tid` rolls out impulse e_tid.
    float wr[64];
    #pragma unroll
    for (int i = 0; i < 64; i++) wr[i] = sh_w[i];

    float win[64];
    const int seed = (64 - tid) & 63;       // a_{-tid} = 1 slot
    #pragma unroll
    for (int p = 0; p < 64; p++) win[p] = (p == seed) ? 1.0f : 0.0f;

    #pragma unroll
    for (int t = 0; t < 64; t++) {
        float n0 = 0.f, n1 = 0.f, n2 = 0.f, n3 = 0.f;
        #pragma unroll
        for (int i = 0; i < 64; i += 4) {
            n0 += wr[i + 0] * win[(t - i - 0) & 63];
            n1 += wr[i + 1] * win[(t - i - 1) & 63];
            n2 += wr[i + 2] * win[(t - i - 2) & 63];
            n3 += wr[i + 3] * win[(t - i - 3) & 63];
        }
        win[(t + 1) & 63] = (n0 + n1) + (n2 + n3);
    }
    #pragma unroll
    for (int i = 0; i < 64; i++) sh_T[i * 65 + tid] = win[(64 - i) & 63];
    __syncthreads();

    // ---- Phase B: 32 chunk matvecs, window V_m -> V_{m+1} = T V_m
    sh_V[tid] = (tid == 0) ? 1.0f : 0.0f;
    if (tid == 0) sh_a[0] = 1.0f;
    __syncthreads();

    for (int m = 0; m < 32; m++) {
        float n0 = 0.f, n1 = 0.f, n2 = 0.f, n3 = 0.f;
        #pragma unroll
        for (int j = 0; j < 64; j += 4) {
            n0 += sh_T[tid * 65 + j + 0] * sh_V[j + 0];
            n1 += sh_T[tid * 65 + j + 1] * sh_V[j + 1];
            n2 += sh_T[tid * 65 + j + 2] * sh_V[j + 2];
            n3 += sh_T[tid * 65 + j + 3] * sh_V[j + 3];
        }
        float nv = (n0 + n1) + (n2 + n3);
        __syncthreads();
        sh_V[tid] = nv;                    // V[i] = a_{64(m+1)-i}
        int idx = 64 * m + 64 - tid;       // a index 64m+1 .. 64m+64
        if (idx < 2048) sh_a[idx] = nv;
        __syncthreads();
    }

    // ---- Phase C: f_t = sum_i g[i] a_{t-i}
    float gr[64];
    #pragma unroll
    for (int i = 0; i < 64; i++) gr[i] = sh_g[i];

    {   // t < 64 with causal bound
        int t = tid;
        float acc = 0.f;
        #pragma unroll
        for (int i = 0; i < 64; i++)
            if (i <= t) acc += gr[i] * sh_a[t - i];
        d_f[h * SEQ + t] = acc;
    }
    for (int q = 1; q < 32; q++) {
        int t = q * 64 + tid;
        float a0 = 0.f, a1 = 0.f, a2 = 0.f, a3 = 0.f;
        #pragma unroll
        for (int i = 0; i < 64; i += 4) {
            a0 += gr[i + 0] * sh_a[t - i - 0];
            a1 += gr[i + 1] * sh_a[t - i - 1];
            a2 += gr[i + 2] * sh_a[t - i - 2];
            a3 += gr[i + 3] * sh_a[t - i - 3];
        }
        d_f[h * SEQ + t] = (a0 + a1) + (a2 + a3);
    }
}

// ---------------------------------------------------------------------------
// Shared-memory radix-2 FFT, N=4096, 256 threads.
// fft_dif: natural in -> bit-reversed out.  ifft_dit: bit-reversed in ->
// natural out (un-normalized; 1/N folded into the spectrum multiply).
// ---------------------------------------------------------------------------
__device__ __forceinline__ void load_tw(float2* tw) {
    for (int i = threadIdx.x; i < NFFT / 2; i += 256) tw[i] = d_tw[i];
}

__device__ __forceinline__ void fft_dif(float2* d, const float2* tw) {
    #pragma unroll
    for (int len = 2048; len >= 1; len >>= 1) {
        const int stride = 2048 / len;
        for (int t = threadIdx.x; t < 2048; t += 256) {
            int off = t & (len - 1);
            int i = 2 * t - off;
            int j = i + len;
            float2 a = d[i], b = d[j];
            d[i] = make_float2(a.x + b.x, a.y + b.y);
            float2 s = make_float2(a.x - b.x, a.y - b.y);
            d[j] = cmul(s, tw[off * stride]);
        }
        __syncthreads();
    }
}

__device__ __forceinline__ void ifft_dit(float2* d, const float2* tw) {
    #pragma unroll
    for (int len = 1; len <= 2048; len <<= 1) {
        const int stride = 2048 / len;
        for (int t = threadIdx.x; t < 2048; t += 256) {
            int off = t & (len - 1);
            int i = 2 * t - off;
            int j = i + len;
            float2 b = d[j];
            float2 w = tw[off * stride];
            // b * conj(w)
            float2 bw = make_float2(b.x * w.x + b.y * w.y, b.y * w.x - b.x * w.y);
            float2 a = d[i];
            d[i] = make_float2(a.x + bw.x, a.y + bw.y);
            d[j] = make_float2(a.x - bw.x, a.y - bw.y);
        }
        __syncthreads();
    }
}

// ---------------------------------------------------------------------------
// Filter spectrum: Fhat[h] = DIF-FFT(pad(f[h])), stored bit-reversed.
// ---------------------------------------------------------------------------
__global__ __launch_bounds__(256) void fft_filter_kernel() {
    extern __shared__ float2 sm[];
    float2* d  = sm;
    float2* tw = sm + NFFT;
    int h = blockIdx.x;

    for (int t = threadIdx.x; t < SEQ; t += 256) {
        d[t]       = make_float2(d_f[h * SEQ + t], 0.f);
        d[t + SEQ] = make_float2(0.f, 0.f);
    }
    load_tw(tw);
    __syncthreads();
    fft_dif(d, tw);
    for (int t = threadIdx.x; t < NFFT; t += 256) d_Fhat[h * NFFT + t] = d[t];
}

// ---------------------------------------------------------------------------
// Convolution: two batches packed per complex FFT (f real => ifft(F*Y) gives
// y_b0 in re, y_b1 in im). Pointwise multiply in bit-reversed order.
// ---------------------------------------------------------------------------
__global__ __launch_bounds__(256) void conv_kernel(const float* __restrict__ u,
                                                   float* __restrict__ y) {
    extern __shared__ float2 sm[];
    float2* d  = sm;
    float2* tw = sm + NFFT;

    const int h  = blockIdx.y;
    const int bp = blockIdx.x;            // batch pair 0..7
    const float* u0 = u + ((size_t)(2 * bp) * NHEADS + h) * SEQ;
    const float* u1 = u0 + (size_t)NHEADS * SEQ;

    for (int t = threadIdx.x; t < SEQ; t += 256) {
        d[t]       = make_float2(u0[t], u1[t]);
        d[t + SEQ] = make_float2(0.f, 0.f);
    }
    load_tw(tw);
    __syncthreads();

    fft_dif(d, tw);

    const float scale = 1.0f / (float)NFFT;
    for (int t = threadIdx.x; t < NFFT; t += 256) {
        float2 p = cmul(d[t], d_Fhat[h * NFFT + t]);
        d[t] = make_float2(p.x * scale, p.y * scale);
    }
    __syncthreads();

    ifft_dit(d, tw);

    float* y0 = y + ((size_t)(2 * bp) * NHEADS + h) * SEQ;
    float* y1 = y0 + (size_t)NHEADS * SEQ;
    for (int t = threadIdx.x; t < SEQ; t += 256) {
        y0[t] = d[t].x;
        y1[t] = d[t].y;
    }
}

// ---------------------------------------------------------------------------
extern "C" void kernel_launch(void* const* d_in, const int* in_sizes, int n_in,
                              void* d_out, int out_size) {
    const float* u = (const float*)d_in[0];
    const float* k = (const float*)d_in[1];
    if (n_in >= 2 && in_sizes[0] < in_sizes[1]) {  // defensive: u is the big one
        const float* t = u; u = k; k = t;
    }
    float* y = (float*)d_out;

    const size_t smem = (size_t)NFFT * sizeof(float2) + (size_t)(NFFT / 2) * sizeof(float2); // 49152

    twiddle_kernel<<<(NFFT / 2 + 255) / 256, 256>>>();
    filter_kernel<<<NHEADS, 64>>>(k);
    fft_filter_kernel<<<NHEADS, 256, smem>>>();
    conv_kernel<<<dim3(NB / 2, NHEADS), 256, smem>>>(u, y);
}

// round 3
// speedup vs baseline: 5.7174x; 5.7174x over previous
#include <cuda_runtime.h>
#include <cuda_bf16.h>

#define NHEADS 512
#define NK     64
#define SEQ    2048
#define NFFT   4096
#define NB     16
#define PITCH  272   // transpose pitch: 16*17, conflict-free for both patterns

// Scratch (static __device__ — no allocation)
__device__ float  d_f[NHEADS * SEQ];
__device__ float2 d_Fhat[NHEADS * NFFT];
__device__ float2 d_tw[NFFT / 2];

__device__ __forceinline__ float2 cadd(float2 a, float2 b){ return make_float2(a.x+b.x, a.y+b.y); }
__device__ __forceinline__ float2 csub(float2 a, float2 b){ return make_float2(a.x-b.x, a.y-b.y); }
__device__ __forceinline__ float2 cmul(float2 a, float2 b){
    return make_float2(a.x*b.x - a.y*b.y, a.x*b.y + a.y*b.x);
}

// multiply by -i (fwd) or +i (inv)
template<int INV>
__device__ __forceinline__ float2 mulj(float2 a){
    return INV ? make_float2(-a.y, a.x) : make_float2(a.y, -a.x);
}

template<int INV>
__device__ __forceinline__ void bfly4(float2& x0, float2& x1, float2& x2, float2& x3){
    float2 ac = cadd(x0, x2), amc = csub(x0, x2);
    float2 bd = cadd(x1, x3), bmd = csub(x1, x3);
    float2 jb = mulj<INV>(bmd);
    x0 = cadd(ac, bd);  x2 = csub(ac, bd);
    x1 = cadd(amc, jb); x3 = csub(amc, jb);
}

// In-place 16-point DFT (INV=1: un-normalized inverse), x[n] -> X[k] at x[k].
template<int INV>
__device__ __forceinline__ void dft16(float2* x){
    const float C1 = 0.9238795325112867f, S1 = 0.3826834323650898f, R = 0.7071067811865476f;
    const float2 W1 = INV ? make_float2( C1,  S1) : make_float2( C1, -S1);
    const float2 W2 = INV ? make_float2(  R,   R) : make_float2(  R,  -R);
    const float2 W3 = INV ? make_float2( S1,  C1) : make_float2( S1, -C1);
    const float2 W6 = INV ? make_float2( -R,   R) : make_float2( -R,  -R);
    const float2 W9 = INV ? make_float2(-C1, -S1) : make_float2(-C1,  S1);

    float2 u[16];   // u[n1*4 + k1]
    #pragma unroll
    for (int n1 = 0; n1 < 4; n1++){
        float2 a = x[n1], b = x[n1+4], c = x[n1+8], d = x[n1+12];
        bfly4<INV>(a, b, c, d);
        u[n1*4+0] = a; u[n1*4+1] = b; u[n1*4+2] = c; u[n1*4+3] = d;
    }
    // twiddle W16^{n1*k1}
    u[5]  = cmul(u[5],  W1);  u[6]  = cmul(u[6],  W2);  u[7]  = cmul(u[7],  W3);
    u[9]  = cmul(u[9],  W2);  u[10] = mulj<INV>(u[10]); u[11] = cmul(u[11], W6);
    u[13] = cmul(u[13], W3);  u[14] = cmul(u[14], W6);  u[15] = cmul(u[15], W9);
    #pragma unroll
    for (int k1 = 0; k1 < 4; k1++){
        float2 a = u[k1], b = u[4+k1], c = u[8+k1], d = u[12+k1];
        bfly4<INV>(a, b, c, d);
        x[k1] = a; x[k1+4] = b; x[k1+8] = c; x[k1+12] = d;
    }
}

// ---------------------------------------------------------------------------
// N=4096 radix-16 FFT, 256 threads, 16 float2 in registers per thread.
// Forward DIF (natural in -> digit-reversed out, thread t holds slots 16t+q).
// Inverse DIT mirrors exactly (digit-reversed in -> natural out).
// ---------------------------------------------------------------------------
__device__ __forceinline__ void fft4096_fwd(float2* r, float2* sh, int t){
    const int o = t & 15, b = t >> 4;
    // stage 1: L=4096, elements t + 256m
    dft16<0>(r);
    { float2 w = d_tw[t], p = w;
      #pragma unroll
      for (int q = 1; q < 16; q++){ r[q] = cmul(r[q], p); p = cmul(p, w); } }
    #pragma unroll
    for (int q = 0; q < 16; q++) sh[PITCH*q + t] = r[q];
    __syncthreads();
    // stage 2: L=256, block b, elements b*256 + o + 16m
    #pragma unroll
    for (int m = 0; m < 16; m++) r[m] = sh[PITCH*b + 16*m + o];
    dft16<0>(r);
    { float2 w = d_tw[16*o], p = w;
      #pragma unroll
      for (int q = 1; q < 16; q++){ r[q] = cmul(r[q], p); p = cmul(p, w); } }
    __syncthreads();
    #pragma unroll
    for (int q = 0; q < 16; q++) sh[PITCH*b + 17*q + o] = r[q];
    __syncthreads();
    // stage 3: L=16, contiguous block t: slots 16t + j
    #pragma unroll
    for (int j = 0; j < 16; j++) r[j] = sh[PITCH*b + 17*o + j];
    dft16<0>(r);   // thread t now holds spectrum at logical slots 16t + q
}

__device__ __forceinline__ void fft4096_inv(float2* r, float2* sh, int t){
    const int o = t & 15, b = t >> 4;
    // inv stage 1: L=16, contiguous, no twiddle
    dft16<1>(r);
    __syncthreads();             // fwd's final reads are done before overwrite
    #pragma unroll
    for (int j = 0; j < 16; j++) sh[PITCH*b + 17*o + j] = r[j];
    __syncthreads();
    // inv stage 2: L=256
    #pragma unroll
    for (int q = 0; q < 16; q++) r[q] = sh[PITCH*b + 17*q + o];
    { float2 tw0 = d_tw[16*o];
      float2 w = make_float2(tw0.x, -tw0.y), p = w;
      #pragma unroll
      for (int q = 1; q < 16; q++){ r[q] = cmul(r[q], p); p = cmul(p, w); } }
    dft16<1>(r);                 // -> slots b*256 + o + 16m
    __syncthreads();
    #pragma unroll
    for (int m = 0; m < 16; m++) sh[PITCH*b + 16*m + o] = r[m];
    __syncthreads();
    // inv stage 3: L=4096
    #pragma unroll
    for (int q = 0; q < 16; q++) r[q] = sh[PITCH*q + t];
    { float2 tw0 = d_tw[t];
      float2 w = make_float2(tw0.x, -tw0.y), p = w;
      #pragma unroll
      for (int q = 1; q < 16; q++){ r[q] = cmul(r[q], p); p = cmul(p, w); } }
    dft16<1>(r);                 // -> natural slots t + 256m
}

// ---------------------------------------------------------------------------
// Twiddle table: d_tw[k] = exp(-2*pi*i*k/4096), k < 2048
// ---------------------------------------------------------------------------
__global__ void twiddle_kernel() {
    int k = blockIdx.x * blockDim.x + threadIdx.x;
    if (k < NFFT / 2) {
        float a = (float)k / (float)(NFFT / 2);
        d_tw[k] = make_float2(cospif(a), -sinpif(a));
    }
}

// ---------------------------------------------------------------------------
// Filter construction (unchanged from R2 — 2.5us class).
// ---------------------------------------------------------------------------
__global__ __launch_bounds__(64) void filter_kernel(const float* __restrict__ kin) {
    __shared__ float sh_kn[64], sh_P[64], sh_w[64], sh_g[64];
    __shared__ float sh_T[64 * 65];
    __shared__ float sh_V[64];
    __shared__ float sh_a[2048];
    __shared__ float part[2];

    const int tid = threadIdx.x;
    const int h   = blockIdx.x;

    float kv = kin[h * NK + tid];
    float kc = fminf(fmaxf(kv, 0.0625f), 1.0f);

    float v = kc;
    #pragma unroll
    for (int o = 16; o; o >>= 1) v += __shfl_xor_sync(0xffffffffu, v, o);
    if ((tid & 31) == 0) part[tid >> 5] = v;
    __syncthreads();
    float kn = kc / (part[0] + part[1]);
    sh_kn[tid] = kn;
    __syncthreads();

    if (tid == 0) {
        float p = 1.0f;
        for (int j = 0; j < 64; j++) {
            sh_P[j] = p;
            if (j < 63) p *= 1.0f / (1.0f + sh_kn[j]);
        }
    }
    __syncthreads();

    float m0 = (tid < 63) ? kn / (1.0f + kn) : 1.0f;
    sh_w[tid] = m0 * sh_P[tid];
    sh_g[tid] = kv * sh_P[tid];
    __syncthreads();

    float wr[64];
    #pragma unroll
    for (int i = 0; i < 64; i++) wr[i] = sh_w[i];

    float win[64];
    const int seed = (64 - tid) & 63;
    #pragma unroll
    for (int p = 0; p < 64; p++) win[p] = (p == seed) ? 1.0f : 0.0f;

    #pragma unroll
    for (int t = 0; t < 64; t++) {
        float n0 = 0.f, n1 = 0.f, n2 = 0.f, n3 = 0.f;
        #pragma unroll
        for (int i = 0; i < 64; i += 4) {
            n0 += wr[i + 0] * win[(t - i - 0) & 63];
            n1 += wr[i + 1] * win[(t - i - 1) & 63];
            n2 += wr[i + 2] * win[(t - i - 2) & 63];
            n3 += wr[i + 3] * win[(t - i - 3) & 63];
        }
        win[(t + 1) & 63] = (n0 + n1) + (n2 + n3);
    }
    #pragma unroll
    for (int i = 0; i < 64; i++) sh_T[i * 65 + tid] = win[(64 - i) & 63];
    __syncthreads();

    sh_V[tid] = (tid == 0) ? 1.0f : 0.0f;
    if (tid == 0) sh_a[0] = 1.0f;
    __syncthreads();

    for (int m = 0; m < 32; m++) {
        float n0 = 0.f, n1 = 0.f, n2 = 0.f, n3 = 0.f;
        #pragma unroll
        for (int j = 0; j < 64; j += 4) {
            n0 += sh_T[tid * 65 + j + 0] * sh_V[j + 0];
            n1 += sh_T[tid * 65 + j + 1] * sh_V[j + 1];
            n2 += sh_T[tid * 65 + j + 2] * sh_V[j + 2];
            n3 += sh_T[tid * 65 + j + 3] * sh_V[j + 3];
        }
        float nv = (n0 + n1) + (n2 + n3);
        __syncthreads();
        sh_V[tid] = nv;
        int idx = 64 * m + 64 - tid;
        if (idx < 2048) sh_a[idx] = nv;
        __syncthreads();
    }

    float gr[64];
    #pragma unroll
    for (int i = 0; i < 64; i++) gr[i] = sh_g[i];

    {
        int t = tid;
        float acc = 0.f;
        #pragma unroll
        for (int i = 0; i < 64; i++)
            if (i <= t) acc += gr[i] * sh_a[t - i];
        d_f[h * SEQ + t] = acc;
    }
    for (int q = 1; q < 32; q++) {
        int t = q * 64 + tid;
        float a0 = 0.f, a1 = 0.f, a2 = 0.f, a3 = 0.f;
        #pragma unroll
        for (int i = 0; i < 64; i += 4) {
            a0 += gr[i + 0] * sh_a[t - i - 0];
            a1 += gr[i + 1] * sh_a[t - i - 1];
            a2 += gr[i + 2] * sh_a[t - i - 2];
            a3 += gr[i + 3] * sh_a[t - i - 3];
        }
        d_f[h * SEQ + t] = (a0 + a1) + (a2 + a3);
    }
}

// ---------------------------------------------------------------------------
// Filter spectrum, stored permuted (thread-major): Fhat[h][q*256+t] holds the
// fwd-FFT digit-reversed slot 16t+q. 1/N folded in here.
// ---------------------------------------------------------------------------
__global__ __launch_bounds__(256) void fft_filter_kernel() {
    __shared__ float2 sh[16 * PITCH];
    float2 r[16];
    const int t = threadIdx.x, h = blockIdx.x;

    #pragma unroll
    for (int q = 0; q < 8; q++)
        r[q] = make_float2(d_f[h * SEQ + t + 256 * q] * (1.0f / NFFT), 0.f);
    #pragma unroll
    for (int q = 8; q < 16; q++) r[q] = make_float2(0.f, 0.f);

    fft4096_fwd(r, sh, t);

    #pragma unroll
    for (int q = 0; q < 16; q++)
        d_Fhat[(size_t)h * NFFT + q * 256 + t] = r[q];
}

// ---------------------------------------------------------------------------
// Convolution: two batches packed per complex FFT (f real). Forward innermost
// stage, pointwise multiply, and inverse innermost stage fused in registers.
// ---------------------------------------------------------------------------
__global__ __launch_bounds__(256) void conv_kernel(const float* __restrict__ u,
                                                   float* __restrict__ y) {
    __shared__ float2 sh[16 * PITCH];
    float2 r[16];
    const int t  = threadIdx.x;
    const int h  = blockIdx.y;
    const int bp = blockIdx.x;
    const float* u0 = u + ((size_t)(2 * bp) * NHEADS + h) * SEQ;
    const float* u1 = u0 + (size_t)NHEADS * SEQ;

    #pragma unroll
    for (int q = 0; q < 8; q++) {
        int idx = t + 256 * q;
        r[q] = make_float2(u0[idx], u1[idx]);
    }
    #pragma unroll
    for (int q = 8; q < 16; q++) r[q] = make_float2(0.f, 0.f);

    fft4096_fwd(r, sh, t);

    const float2* Fh = d_Fhat + (size_t)h * NFFT;
    #pragma unroll
    for (int q = 0; q < 16; q++)
        r[q] = cmul(r[q], __ldg(&Fh[q * 256 + t]));

    fft4096_inv(r, sh, t);

    float* y0 = y + ((size_t)(2 * bp) * NHEADS + h) * SEQ;
    float* y1 = y0 + (size_t)NHEADS * SEQ;
    #pragma unroll
    for (int m = 0; m < 8; m++) {
        int idx = t + 256 * m;
        y0[idx] = r[m].x;
        y1[idx] = r[m].y;
    }
}

// ---------------------------------------------------------------------------
extern "C" void kernel_launch(void* const* d_in, const int* in_sizes, int n_in,
                              void* d_out, int out_size) {
    const float* u = (const float*)d_in[0];
    const float* k = (const float*)d_in[1];
    if (n_in >= 2 && in_sizes[0] < in_sizes[1]) {
        const float* t = u; u = k; k = t;
    }
    float* y = (float*)d_out;

    twiddle_kernel<<<(NFFT / 2 + 255) / 256, 256>>>();
    filter_kernel<<<NHEADS, 64>>>(k);
    fft_filter_kernel<<<NHEADS, 256>>>();
    conv_kernel<<<dim3(NB / 2, NHEADS), 256>>>(u, y);
}